// round 15
// baseline (speedup 1.0000x reference)
#include <cuda_runtime.h>
#include <cuda_fp16.h>
#include <cstdint>

// ============================================================================
// untied LSTM cell, GB300 — plain sm_103 target (no tcgen05 in this harness).
// fp16 mma.sync m16n8k16 + ldmatrix.x4, 3-stage cp.async pipeline, XOR swizzle,
// 2 CTAs/SM (tile 128x128, warp tile 32x64, TK=64).
// R15 vs R14 (145.6, reg-spill regression): revert to R13's single-buffered
// fragment loop (proven 125.7, ~110 regs); move the cp.async issue() to after
// the first LDSM group (fills its latency window at zero register cost);
// widen prep/pointwise to 8 elems/thread with uint4 traffic.
// ============================================================================

#define B_DIM 2048
#define H_DIM 1024
#define BH (B_DIM * H_DIM)
#define HH (H_DIM * H_DIM)

__device__ __align__(16) __half g_g16 [4u * BH];    // gate pre-acts fp16 (16MB)
__device__ __align__(16) __half g_x16 [BH];         // x fp16 (4 MB)
__device__ __align__(16) __half g_hm16[4u * BH];    // h0*mask[g] fp16 (16 MB)
__device__ __align__(16) __half g_w16 [8u * HH];    // Wx[4],Wh[4] fp16 (16 MB)

// ---------------- PTX helpers ----------------------------------------------

__device__ __forceinline__ uint32_t smem_u32(const void* p) {
    uint32_t a;
    asm("{ .reg .u64 t; cvta.to.shared.u64 t, %1; cvt.u32.u64 %0, t; }"
        : "=r"(a) : "l"(p));
    return a;
}

__device__ __forceinline__ void cp_async16(void* sdst, const void* gsrc) {
    asm volatile("cp.async.cg.shared.global [%0], [%1], 16;"
                 :: "r"(smem_u32(sdst)), "l"(gsrc));
}
__device__ __forceinline__ void cp_commit() {
    asm volatile("cp.async.commit_group;" ::: "memory");
}
template <int N>
__device__ __forceinline__ void cp_wait() {
    asm volatile("cp.async.wait_group %0;" :: "n"(N) : "memory");
}

__device__ __forceinline__ void ldm_x4(uint32_t* r, uint32_t addr) {
    asm volatile("ldmatrix.sync.aligned.m8n8.x4.shared.b16 {%0,%1,%2,%3}, [%4];"
                 : "=r"(r[0]), "=r"(r[1]), "=r"(r[2]), "=r"(r[3]) : "r"(addr));
}

__device__ __forceinline__ void mma_f16(float* c, const uint32_t* a,
                                        const uint32_t* b) {
    asm volatile(
        "mma.sync.aligned.m16n8k16.row.col.f32.f16.f16.f32 "
        "{%0,%1,%2,%3}, {%4,%5,%6,%7}, {%8,%9}, {%0,%1,%2,%3};"
        : "+f"(c[0]), "+f"(c[1]), "+f"(c[2]), "+f"(c[3])
        : "r"(a[0]), "r"(a[1]), "r"(a[2]), "r"(a[3]), "r"(b[0]), "r"(b[1]));
}

__device__ __forceinline__ uint32_t pack_h2(float lo, float hi) {
    const __half2 h = __float22half2_rn(make_float2(lo, hi));
    return *(const uint32_t*)&h;
}

// ---------------- GEMM config ----------------------------------------------
// Rows are exactly 128B; column-block cb (0..7, 16B each) is XOR-swizzled
// with (row & 7): conflict-free for both cp.async stores and ldmatrix reads.

static constexpr int TM = 128, TN = 128, TK = 64;
static constexpr int STAGES = 3;
static constexpr int A_BYTES = TM * 128;            // 16384
static constexpr int B_BYTES = TN * 128;            // 16384
static constexpr int STAGE_BYTES = A_BYTES + B_BYTES;       // 32768
static constexpr int SMEM_BYTES = STAGES * STAGE_BYTES;     // 98304 (x2 CTA ok)

// ---------------- GEMM kernel: 256 thr, 2 CTA/SM, warp tile 32x64 -----------

__global__ void __launch_bounds__(256, 2)
lstm_gemm()
{
    extern __shared__ char smc[];
    const int tid  = threadIdx.x;
    const int lane = tid & 31;
    const int wid  = tid >> 5;          // 0..7
    const int wm   = wid >> 1;          // 0..3  (M warps, 32 rows)
    const int wn   = wid & 1;           // 0..1  (N warps, 64 cols)
    const int n_tile = blockIdx.x;      // 0..7
    const int m_tile = blockIdx.y;      // 0..15
    const int gate   = blockIdx.z;      // 0..3

    const int arow0 = m_tile * TM;
    const int brow0 = n_tile * TN;
    const __half* xsrc  = g_x16;
    const __half* hsrc  = g_hm16 + (size_t)gate * BH;
    const __half* wxsrc = g_w16 + (size_t)gate * HH;
    const __half* whsrc = g_w16 + (size_t)(4 + gate) * HH;

    // 32 chunks of K=64: 0..15 from x/Wx, 16..31 from hm/Wh
    auto issue = [&](int chunk, int stage) {
        const int kc = (chunk & 15) * TK;                 // halves
        const __half* Asrc = (chunk < 16) ? xsrc : hsrc;
        const __half* Bsrc = (chunk < 16) ? wxsrc : whsrc;
        char* As = smc + stage * STAGE_BYTES;
        char* Bs = As + A_BYTES;
        #pragma unroll
        for (int r = 0; r < 4; ++r) {                     // A: 1024 x 16B
            const int pos = tid + r * 256;
            const int row = pos >> 3, cb = pos & 7;
            cp_async16(As + row * 128 + ((cb ^ (row & 7)) << 4),
                       (const char*)(Asrc + (size_t)(arow0 + row) * 1024 + kc)
                           + cb * 16);
        }
        #pragma unroll
        for (int r = 0; r < 4; ++r) {                     // B: 1024 x 16B
            const int pos = tid + r * 256;
            const int row = pos >> 3, cb = pos & 7;
            cp_async16(Bs + row * 128 + ((cb ^ (row & 7)) << 4),
                       (const char*)(Bsrc + (size_t)(brow0 + row) * 1024 + kc)
                           + cb * 16);
        }
    };

    float acc[2][8][4];
    #pragma unroll
    for (int i = 0; i < 2; ++i)
        #pragma unroll
        for (int j = 0; j < 8; ++j)
            #pragma unroll
            for (int k = 0; k < 4; ++k) acc[i][j][k] = 0.f;

    issue(0, 0); cp_commit();
    issue(1, 1); cp_commit();

    // ldmatrix lane bases. XOR key is (lane & 7) for every fragment this lane
    // touches (all row offsets within a fragment are multiples of 8 rows).
    const int      swz_key = lane & 7;
    const uint32_t a_row   = (uint32_t)(wm * 32 + (lane & 15)) * 128;
    const int      a_cb0   = lane >> 4;                   // 0/1
    const uint32_t b_row   = (uint32_t)(wn * 64 + (lane & 7) +
                                        ((lane >> 4) << 3)) * 128;
    const int      b_cb0   = (lane >> 3) & 1;             // 0/1
    const uint32_t sm_base = smem_u32(smc);

    // single-buffered fragments (R13 register budget: ~110, no spills)
    uint32_t af[2][4], bq[4][4];

    #define LOAD_FRAGS(ks, a_base, b_base) do {                             \
        const uint32_t a_sw =                                               \
            (uint32_t)((((ks) * 2 + a_cb0) ^ swz_key) << 4);                \
        const uint32_t b_sw =                                               \
            (uint32_t)((((ks) * 2 + b_cb0) ^ swz_key) << 4);                \
        ldm_x4(af[0], (a_base) + 0u * 16 * 128 + a_sw);                     \
        ldm_x4(af[1], (a_base) + 1u * 16 * 128 + a_sw);                     \
        ldm_x4(bq[0], (b_base) + 0u * 16 * 128 + b_sw);                     \
        ldm_x4(bq[1], (b_base) + 1u * 16 * 128 + b_sw);                     \
        ldm_x4(bq[2], (b_base) + 2u * 16 * 128 + b_sw);                     \
        ldm_x4(bq[3], (b_base) + 3u * 16 * 128 + b_sw);                     \
    } while (0)

    for (int c = 0; c < 32; ++c) {
        cp_wait<1>();
        __syncthreads();

        const uint32_t stg = sm_base + (c % STAGES) * STAGE_BYTES;
        const uint32_t a_base = stg + a_row;
        const uint32_t b_base = stg + A_BYTES + b_row;

        // first LDSM group, then the cp.async prefetch burst fills its
        // latency window (zero register cost vs R13, same instruction set).
        LOAD_FRAGS(0, a_base, b_base);
        if (c + 2 < 32) issue(c + 2, (c + 2) % STAGES);
        cp_commit();

        #pragma unroll
        for (int ks = 0; ks < 4; ++ks) {                  // K=16 per step
            #pragma unroll
            for (int mf = 0; mf < 2; ++mf)
                #pragma unroll
                for (int nf = 0; nf < 8; ++nf)
                    mma_f16(acc[mf][nf], af[mf],
                            &bq[nf >> 1][(nf & 1) * 2]);
            if (ks < 3) LOAD_FRAGS(ks + 1, a_base, b_base);
        }
    }
    #undef LOAD_FRAGS

    // epilogue: pre-activations -> fp16 scratch
    const int g = lane >> 2, t2 = (lane & 3) * 2;
    #pragma unroll
    for (int mf = 0; mf < 2; ++mf) {
        const int row = arow0 + wm * 32 + mf * 16 + g;
        __half* orow = g_g16 + ((size_t)gate * B_DIM + row) * H_DIM + brow0;
        #pragma unroll
        for (int nf = 0; nf < 8; ++nf) {
            const int col = wn * 64 + nf * 8 + t2;
            *(uint32_t*)(orow + col) =
                pack_h2(acc[mf][nf][0], acc[mf][nf][1]);
            *(uint32_t*)(orow + col + 8 * H_DIM) =
                pack_h2(acc[mf][nf][2], acc[mf][nf][3]);
        }
    }
}

// ------- fused pre-pass: x->fp16, hm[g]=h0*mask[g]->fp16, weights->fp16 -----
// part 1: 1024 blocks, 8 elems/thread (x + 4 gate hm)
// part 2: 4096 blocks, 8 floats/thread (weight conversion)

__global__ void __launch_bounds__(256)
prep_kernel(const float* __restrict__ x,  const float* __restrict__ h0,
            const float* __restrict__ mi, const float* __restrict__ mf,
            const float* __restrict__ mc, const float* __restrict__ mo,
            const float* __restrict__ wxi, const float* __restrict__ wxf,
            const float* __restrict__ wxc, const float* __restrict__ wxo,
            const float* __restrict__ whi, const float* __restrict__ whf,
            const float* __restrict__ whc, const float* __restrict__ who)
{
    const int bid = blockIdx.x;
    if (bid < 1024) {                               // x + hm part (BH/8 elems)
        const int i = bid * 256 + threadIdx.x;      // uint4 (8-half) index
        const float4 xv0 = ((const float4*)x)[2 * i];
        const float4 xv1 = ((const float4*)x)[2 * i + 1];
        ((uint4*)g_x16)[i] =
            make_uint4(pack_h2(xv0.x, xv0.y), pack_h2(xv0.z, xv0.w),
                       pack_h2(xv1.x, xv1.y), pack_h2(xv1.z, xv1.w));
        const float4 h0v = ((const float4*)h0)[2 * i];
        const float4 h1v = ((const float4*)h0)[2 * i + 1];
        const float* Ms[4] = { mi, mf, mc, mo };
        #pragma unroll
        for (int gate = 0; gate < 4; ++gate) {
            const float4 m0 = ((const float4*)Ms[gate])[2 * i];
            const float4 m1 = ((const float4*)Ms[gate])[2 * i + 1];
            ((uint4*)(g_hm16 + (size_t)gate * BH))[i] =
                make_uint4(pack_h2(h0v.x * m0.x, h0v.y * m0.y),
                           pack_h2(h0v.z * m0.z, h0v.w * m0.w),
                           pack_h2(h1v.x * m1.x, h1v.y * m1.y),
                           pack_h2(h1v.z * m1.z, h1v.w * m1.w));
        }
    } else {                                        // weight conversion part
        const int wb = bid - 1024;                  // 0..4095
        const int m = wb >> 9;                      // matrix 0..7
        const float* src =
            m == 0 ? wxi : m == 1 ? wxf : m == 2 ? wxc : m == 3 ? wxo :
            m == 4 ? whi : m == 5 ? whf : m == 6 ? whc : who;
        const int off = ((wb & 511) * 256 + threadIdx.x) * 8;
        const float4 v0 = *(const float4*)(src + off);
        const float4 v1 = *(const float4*)(src + off + 4);
        *(uint4*)(g_w16 + (size_t)m * HH + off) =
            make_uint4(pack_h2(v0.x, v0.y), pack_h2(v0.z, v0.w),
                       pack_h2(v1.x, v1.y), pack_h2(v1.z, v1.w));
    }
}

// ---------------- pointwise LSTM epilogue (8 elems/thread) ------------------

__device__ __forceinline__ float sigf(float v) {
    return 1.0f / (1.0f + __expf(-v));
}

__global__ void __launch_bounds__(256)
lstm_pointwise(const float* __restrict__ c0,
               const float* __restrict__ bi, const float* __restrict__ bf,
               const float* __restrict__ bc, const float* __restrict__ bo,
               const float* __restrict__ maskC, float* __restrict__ out)
{
    const int i8 = blockIdx.x * blockDim.x + threadIdx.x;   // over BH/8
    if (i8 >= BH / 8) return;
    const int k8 = i8 & (H_DIM / 8 - 1);

    const uint4 gi = ((const uint4*)(g_g16 + 0 * (size_t)BH))[i8];
    const uint4 gf = ((const uint4*)(g_g16 + 1 * (size_t)BH))[i8];
    const uint4 gc = ((const uint4*)(g_g16 + 2 * (size_t)BH))[i8];
    const uint4 go = ((const uint4*)(g_g16 + 3 * (size_t)BH))[i8];

    float GI[8], GF[8], GC[8], GO[8];
    #define UNPK(dst, src) do { \
        float2 t; \
        t = __half22float2(*(const __half2*)&(src).x); dst[0]=t.x; dst[1]=t.y; \
        t = __half22float2(*(const __half2*)&(src).y); dst[2]=t.x; dst[3]=t.y; \
        t = __half22float2(*(const __half2*)&(src).z); dst[4]=t.x; dst[5]=t.y; \
        t = __half22float2(*(const __half2*)&(src).w); dst[6]=t.x; dst[7]=t.y; \
    } while (0)
    UNPK(GI, gi); UNPK(GF, gf); UNPK(GC, gc); UNPK(GO, go);
    #undef UNPK

    const float4 BI0 = ((const float4*)bi)[2 * k8];
    const float4 BI1 = ((const float4*)bi)[2 * k8 + 1];
    const float4 BF0 = ((const float4*)bf)[2 * k8];
    const float4 BF1 = ((const float4*)bf)[2 * k8 + 1];
    const float4 BC0 = ((const float4*)bc)[2 * k8];
    const float4 BC1 = ((const float4*)bc)[2 * k8 + 1];
    const float4 BO0 = ((const float4*)bo)[2 * k8];
    const float4 BO1 = ((const float4*)bo)[2 * k8 + 1];
    const float4 C00 = ((const float4*)c0)[2 * i8];
    const float4 C01 = ((const float4*)c0)[2 * i8 + 1];
    const float4 MC0 = ((const float4*)maskC)[2 * i8];
    const float4 MC1 = ((const float4*)maskC)[2 * i8 + 1];

    const float BIv[8] = { BI0.x,BI0.y,BI0.z,BI0.w, BI1.x,BI1.y,BI1.z,BI1.w };
    const float BFv[8] = { BF0.x,BF0.y,BF0.z,BF0.w, BF1.x,BF1.y,BF1.z,BF1.w };
    const float BCv[8] = { BC0.x,BC0.y,BC0.z,BC0.w, BC1.x,BC1.y,BC1.z,BC1.w };
    const float BOv[8] = { BO0.x,BO0.y,BO0.z,BO0.w, BO1.x,BO1.y,BO1.z,BO1.w };
    const float C0v[8] = { C00.x,C00.y,C00.z,C00.w, C01.x,C01.y,C01.z,C01.w };
    const float MCv[8] = { MC0.x,MC0.y,MC0.z,MC0.w, MC1.x,MC1.y,MC1.z,MC1.w };

    float h1[8], c1[8];
    #pragma unroll
    for (int j = 0; j < 8; ++j) {
        const float I = sigf(GI[j] + BIv[j]);
        const float F = sigf(GF[j] + BFv[j]);
        const float C = tanhf(GC[j] + BCv[j]) * MCv[j];
        const float O = sigf(GO[j] + BOv[j]);
        const float cc = F * C0v[j] + I * C;
        c1[j] = cc;
        h1[j] = O * tanhf(cc);
    }

    float4* outv = (float4*)out;
    outv[2 * i8]              = make_float4(h1[0], h1[1], h1[2], h1[3]);
    outv[2 * i8 + 1]          = make_float4(h1[4], h1[5], h1[6], h1[7]);
    outv[BH / 4 + 2 * i8]     = make_float4(c1[0], c1[1], c1[2], c1[3]);
    outv[BH / 4 + 2 * i8 + 1] = make_float4(c1[4], c1[5], c1[6], c1[7]);
}

// ---------------- launch ----------------------------------------------------

extern "C" void kernel_launch(void* const* d_in, const int* in_sizes, int n_in,
                              void* d_out, int out_size)
{
    const float* x     = (const float*)d_in[0];
    const float* h0    = (const float*)d_in[1];
    const float* c0    = (const float*)d_in[2];
    const float* w_xi  = (const float*)d_in[3];
    const float* w_xf  = (const float*)d_in[4];
    const float* w_xc  = (const float*)d_in[5];
    const float* w_xo  = (const float*)d_in[6];
    const float* w_hi  = (const float*)d_in[7];
    const float* w_hf  = (const float*)d_in[8];
    const float* w_hc  = (const float*)d_in[9];
    const float* w_ho  = (const float*)d_in[10];
    const float* b_i   = (const float*)d_in[11];
    const float* b_f   = (const float*)d_in[12];
    const float* b_c   = (const float*)d_in[13];
    const float* b_o   = (const float*)d_in[14];
    const float* mHI   = (const float*)d_in[15];
    const float* mHF   = (const float*)d_in[16];
    const float* mHC   = (const float*)d_in[17];
    const float* mHO   = (const float*)d_in[18];
    const float* maskC = (const float*)d_in[19];

    prep_kernel<<<1024 + 4096, 256>>>(x, h0, mHI, mHF, mHC, mHO,
                                      w_xi, w_xf, w_xc, w_xo,
                                      w_hi, w_hf, w_hc, w_ho);

    cudaFuncSetAttribute(lstm_gemm,
                         cudaFuncAttributeMaxDynamicSharedMemorySize, SMEM_BYTES);
    dim3 grid(H_DIM / TN, B_DIM / TM, 4);   // (8, 16, 4) = 512 CTAs
    lstm_gemm<<<grid, 256, SMEM_BYTES>>>();

    const int n8 = BH / 8;
    lstm_pointwise<<<(n8 + 255) / 256, 256>>>(c0, b_i, b_f, b_c, b_o, maskC,
                                              (float*)d_out);
}

// round 16
// speedup vs baseline: 1.7424x; 1.7424x over previous
#include <cuda_runtime.h>
#include <cuda_fp16.h>
#include <cstdint>

// ============================================================================
// untied LSTM cell, GB300 — plain sm_103 target (no tcgen05 in this harness).
// fp16 mma.sync m16n8k16 + ldmatrix.x4, 3-stage cp.async pipeline, XOR swizzle,
// 2 CTAs/SM (tile 128x128, warp tile 32x64, TK=64).
// R16 vs R15 (211us spill) / R13 (best 125.7): compute body = R13 verbatim
// (the only schedule that fits 128 regs). Sync replaced: per-chunk
// cp_wait+__syncthreads -> mbarrier full/empty ring (cp.async.mbarrier.
// arrive.noinc producers, per-thread arrive consumers). Warps decouple by up
// to one stage, staggering LDSM vs mma phases instead of bursting in lockstep.
// ============================================================================

#define B_DIM 2048
#define H_DIM 1024
#define BH (B_DIM * H_DIM)
#define HH (H_DIM * H_DIM)

__device__ __align__(16) __half g_g16 [4u * BH];    // gate pre-acts fp16 (16MB)
__device__ __align__(16) __half g_x16 [BH];         // x fp16 (4 MB)
__device__ __align__(16) __half g_hm16[4u * BH];    // h0*mask[g] fp16 (16 MB)
__device__ __align__(16) __half g_w16 [8u * HH];    // Wx[4],Wh[4] fp16 (16 MB)

// ---------------- PTX helpers ----------------------------------------------

__device__ __forceinline__ uint32_t smem_u32(const void* p) {
    uint32_t a;
    asm("{ .reg .u64 t; cvta.to.shared.u64 t, %1; cvt.u32.u64 %0, t; }"
        : "=r"(a) : "l"(p));
    return a;
}

__device__ __forceinline__ void cp_async16(void* sdst, const void* gsrc) {
    asm volatile("cp.async.cg.shared.global [%0], [%1], 16;"
                 :: "r"(smem_u32(sdst)), "l"(gsrc));
}

__device__ __forceinline__ void ldm_x4(uint32_t* r, uint32_t addr) {
    asm volatile("ldmatrix.sync.aligned.m8n8.x4.shared.b16 {%0,%1,%2,%3}, [%4];"
                 : "=r"(r[0]), "=r"(r[1]), "=r"(r[2]), "=r"(r[3]) : "r"(addr));
}

__device__ __forceinline__ void mma_f16(float* c, const uint32_t* a,
                                        const uint32_t* b) {
    asm volatile(
        "mma.sync.aligned.m16n8k16.row.col.f32.f16.f16.f32 "
        "{%0,%1,%2,%3}, {%4,%5,%6,%7}, {%8,%9}, {%0,%1,%2,%3};"
        : "+f"(c[0]), "+f"(c[1]), "+f"(c[2]), "+f"(c[3])
        : "r"(a[0]), "r"(a[1]), "r"(a[2]), "r"(a[3]), "r"(b[0]), "r"(b[1]));
}

__device__ __forceinline__ uint32_t pack_h2(float lo, float hi) {
    const __half2 h = __float22half2_rn(make_float2(lo, hi));
    return *(const uint32_t*)&h;
}

// ---------------- mbarrier helpers (all non-'a', proven to compile in R5) ---

#define MBARRIER_INIT(mbar, count) \
    asm volatile("mbarrier.init.shared.b64 [%0], %1;" \
                 :: "r"((uint32_t)(mbar)), "r"((uint32_t)(count)) : "memory")

#define MBARRIER_ARRIVE(mbar) \
    asm volatile("{ .reg .b64 t; mbarrier.arrive.shared.b64 t, [%0]; }" \
                 :: "r"((uint32_t)(mbar)) : "memory")

#define CP_MBAR_ARRIVE_NOINC(mbar) \
    asm volatile("cp.async.mbarrier.arrive.noinc.shared.b64 [%0];" \
                 :: "r"((uint32_t)(mbar)) : "memory")

#define MBARRIER_WAIT_PARITY(mbar_addr, phase_parity) do { \
    uint32_t _mbar = (uint32_t)(mbar_addr); \
    uint32_t _parity = (uint32_t)(phase_parity); \
    uint32_t _done; \
    asm volatile( \
        "{\n\t.reg .pred p;\n\t" \
        "mbarrier.try_wait.parity.acquire.cta.shared::cta.b64 p, [%1], %2;\n\t" \
        "selp.b32 %0, 1, 0, p;\n\t}" \
        : "=r"(_done) : "r"(_mbar), "r"(_parity) : "memory"); \
    if (!_done) { \
        asm volatile( \
            "{\n\t.reg .pred P1;\n\t" \
            "WAIT_LOOP_%=:\n\t" \
            "mbarrier.try_wait.parity.acquire.cta.shared::cta.b64 P1, [%0], %1, 0x989680;\n\t" \
            "@P1 bra.uni WAIT_DONE_%=;\n\t" \
            "bra.uni WAIT_LOOP_%=;\n\t" \
            "WAIT_DONE_%=:\n\t}" \
            :: "r"(_mbar), "r"(_parity) : "memory"); \
    } \
} while (0)

// ---------------- GEMM config ----------------------------------------------
// Rows are exactly 128B; column-block cb (0..7, 16B each) is XOR-swizzled
// with (row & 7): conflict-free for both cp.async stores and ldmatrix reads.

static constexpr int TM = 128, TN = 128, TK = 64;
static constexpr int STAGES = 3;
static constexpr int A_BYTES = TM * 128;            // 16384
static constexpr int B_BYTES = TN * 128;            // 16384
static constexpr int STAGE_BYTES = A_BYTES + B_BYTES;       // 32768
static constexpr int MBAR_OFF   = STAGES * STAGE_BYTES;     // 98304
static constexpr int SMEM_BYTES = MBAR_OFF + 64;            // 98368 (x2 CTA ok)

// ---------------- GEMM kernel: 256 thr, 2 CTA/SM, warp tile 32x64 -----------

__global__ void __launch_bounds__(256, 2)
lstm_gemm()
{
    extern __shared__ char smc[];
    const int tid  = threadIdx.x;
    const int lane = tid & 31;
    const int wid  = tid >> 5;          // 0..7
    const int wm   = wid >> 1;          // 0..3  (M warps, 32 rows)
    const int wn   = wid & 1;           // 0..1  (N warps, 64 cols)
    const int n_tile = blockIdx.x;      // 0..7
    const int m_tile = blockIdx.y;      // 0..15
    const int gate   = blockIdx.z;      // 0..3

    const int arow0 = m_tile * TM;
    const int brow0 = n_tile * TN;
    const __half* xsrc  = g_x16;
    const __half* hsrc  = g_hm16 + (size_t)gate * BH;
    const __half* wxsrc = g_w16 + (size_t)gate * HH;
    const __half* whsrc = g_w16 + (size_t)(4 + gate) * HH;

    const uint32_t sm_base  = smem_u32(smc);
    const uint32_t mb_full  = sm_base + MBAR_OFF;        // full[s]  = +s*8
    const uint32_t mb_empty = sm_base + MBAR_OFF + 24;   // empty[s] = +s*8

    if (tid == 0) {
        #pragma unroll
        for (int s = 0; s < STAGES; ++s) {
            MBARRIER_INIT(mb_full  + s * 8, 256);
            MBARRIER_INIT(mb_empty + s * 8, 256);
        }
    }
    __syncthreads();                    // init visible before any arrive

    // 32 chunks of K=64: 0..15 from x/Wx, 16..31 from hm/Wh
    auto issue = [&](int chunk, int stage) {
        const int kc = (chunk & 15) * TK;                 // halves
        const __half* Asrc = (chunk < 16) ? xsrc : hsrc;
        const __half* Bsrc = (chunk < 16) ? wxsrc : whsrc;
        char* As = smc + stage * STAGE_BYTES;
        char* Bs = As + A_BYTES;
        #pragma unroll
        for (int r = 0; r < 4; ++r) {                     // A: 1024 x 16B
            const int pos = tid + r * 256;
            const int row = pos >> 3, cb = pos & 7;
            cp_async16(As + row * 128 + ((cb ^ (row & 7)) << 4),
                       (const char*)(Asrc + (size_t)(arow0 + row) * 1024 + kc)
                           + cb * 16);
        }
        #pragma unroll
        for (int r = 0; r < 4; ++r) {                     // B: 1024 x 16B
            const int pos = tid + r * 256;
            const int row = pos >> 3, cb = pos & 7;
            cp_async16(Bs + row * 128 + ((cb ^ (row & 7)) << 4),
                       (const char*)(Bsrc + (size_t)(brow0 + row) * 1024 + kc)
                           + cb * 16);
        }
    };

    float acc[2][8][4];
    #pragma unroll
    for (int i = 0; i < 2; ++i)
        #pragma unroll
        for (int j = 0; j < 8; ++j)
            #pragma unroll
            for (int k = 0; k < 4; ++k) acc[i][j][k] = 0.f;

    // prologue: chunks 0,1 -> stages 0,1 (first uses: no empty wait)
    issue(0, 0); CP_MBAR_ARRIVE_NOINC(mb_full + 0 * 8);
    issue(1, 1); CP_MBAR_ARRIVE_NOINC(mb_full + 1 * 8);

    // ldmatrix lane bases. XOR key is (lane & 7) for every fragment this lane
    // touches (all row offsets within a fragment are multiples of 8 rows).
    const int      swz_key = lane & 7;
    const uint32_t a_row   = (uint32_t)(wm * 32 + (lane & 15)) * 128;
    const int      a_cb0   = lane >> 4;                   // 0/1
    const uint32_t b_row   = (uint32_t)(wn * 64 + (lane & 7) +
                                        ((lane >> 4) << 3)) * 128;
    const int      b_cb0   = (lane >> 3) & 1;             // 0/1

    // single-buffered fragments (R13 register budget, no spills)
    uint32_t af[2][4], bq[4][4];

    #define LOAD_FRAGS(ks, a_base, b_base) do {                             \
        const uint32_t a_sw =                                               \
            (uint32_t)((((ks) * 2 + a_cb0) ^ swz_key) << 4);                \
        const uint32_t b_sw =                                               \
            (uint32_t)((((ks) * 2 + b_cb0) ^ swz_key) << 4);                \
        ldm_x4(af[0], (a_base) + 0u * 16 * 128 + a_sw);                     \
        ldm_x4(af[1], (a_base) + 1u * 16 * 128 + a_sw);                     \
        ldm_x4(bq[0], (b_base) + 0u * 16 * 128 + b_sw);                     \
        ldm_x4(bq[1], (b_base) + 1u * 16 * 128 + b_sw);                     \
        ldm_x4(bq[2], (b_base) + 2u * 16 * 128 + b_sw);                     \
        ldm_x4(bq[3], (b_base) + 3u * 16 * 128 + b_sw);                     \
    } while (0)

    int s = 0, u = 0;                   // stage = c % 3, use = c / 3
    int s2 = 2, u2 = 0;                 // for chunk c + 2

    for (int c = 0; c < 32; ++c) {
        // consumer: wait until stage s holds chunk c
        MBARRIER_WAIT_PARITY(mb_full + s * 8, u & 1);

        const uint32_t stg = sm_base + (uint32_t)(s * STAGE_BYTES);
        const uint32_t a_base = stg + a_row;
        const uint32_t b_base = stg + A_BYTES + b_row;

        #pragma unroll
        for (int ks = 0; ks < 4; ++ks) {                  // K=16 per step
            LOAD_FRAGS(ks, a_base, b_base);
            #pragma unroll
            for (int mf = 0; mf < 2; ++mf)
                #pragma unroll
                for (int nf = 0; nf < 8; ++nf)
                    mma_f16(acc[mf][nf], af[mf],
                            &bq[nf >> 1][(nf & 1) * 2]);
        }

        // done reading stage s (mma issue implies LDSM data landed)
        MBARRIER_ARRIVE(mb_empty + s * 8);

        // producer: refill stage s2 with chunk c+2 once its old readers done
        if (c + 2 < 32) {
            if (u2 > 0)
                MBARRIER_WAIT_PARITY(mb_empty + s2 * 8, (u2 - 1) & 1);
            issue(c + 2, s2);
            CP_MBAR_ARRIVE_NOINC(mb_full + s2 * 8);
        }

        if (++s == STAGES) { s = 0; ++u; }
        if (++s2 == STAGES) { s2 = 0; ++u2; }
    }
    #undef LOAD_FRAGS

    // epilogue: pre-activations -> fp16 scratch
    const int g = lane >> 2, t2 = (lane & 3) * 2;
    #pragma unroll
    for (int mf = 0; mf < 2; ++mf) {
        const int row = arow0 + wm * 32 + mf * 16 + g;
        __half* orow = g_g16 + ((size_t)gate * B_DIM + row) * H_DIM + brow0;
        #pragma unroll
        for (int nf = 0; nf < 8; ++nf) {
            const int col = wn * 64 + nf * 8 + t2;
            *(uint32_t*)(orow + col) =
                pack_h2(acc[mf][nf][0], acc[mf][nf][1]);
            *(uint32_t*)(orow + col + 8 * H_DIM) =
                pack_h2(acc[mf][nf][2], acc[mf][nf][3]);
        }
    }
}

// ------- fused pre-pass: x->fp16, hm[g]=h0*mask[g]->fp16, weights->fp16 -----
// (R13 version: 2048 + 4096 blocks, proven 17.0us)

__global__ void __launch_bounds__(256)
prep_kernel(const float* __restrict__ x,  const float* __restrict__ h0,
            const float* __restrict__ mi, const float* __restrict__ mf,
            const float* __restrict__ mc, const float* __restrict__ mo,
            const float* __restrict__ wxi, const float* __restrict__ wxf,
            const float* __restrict__ wxc, const float* __restrict__ wxo,
            const float* __restrict__ whi, const float* __restrict__ whf,
            const float* __restrict__ whc, const float* __restrict__ who)
{
    const int bid = blockIdx.x;
    if (bid < 2048) {                               // x + hm part (BH/4 elems)
        const int i = bid * 256 + threadIdx.x;
        const float4 xv = ((const float4*)x)[i];
        ((uint2*)g_x16)[i] =
            make_uint2(pack_h2(xv.x, xv.y), pack_h2(xv.z, xv.w));
        const float4 h = ((const float4*)h0)[i];
        const float4 M[4] = { ((const float4*)mi)[i], ((const float4*)mf)[i],
                              ((const float4*)mc)[i], ((const float4*)mo)[i] };
        #pragma unroll
        for (int gate = 0; gate < 4; ++gate) {
            ((uint2*)(g_hm16 + (size_t)gate * BH))[i] =
                make_uint2(pack_h2(h.x * M[gate].x, h.y * M[gate].y),
                           pack_h2(h.z * M[gate].z, h.w * M[gate].w));
        }
    } else {                                        // weight conversion part
        const int wb = bid - 2048;                  // 0..4095
        const int m = wb >> 9;                      // matrix 0..7
        const float* src =
            m == 0 ? wxi : m == 1 ? wxf : m == 2 ? wxc : m == 3 ? wxo :
            m == 4 ? whi : m == 5 ? whf : m == 6 ? whc : who;
        const int off = ((wb & 511) * 256 + threadIdx.x) * 8;
        const float4 v0 = *(const float4*)(src + off);
        const float4 v1 = *(const float4*)(src + off + 4);
        *(uint4*)(g_w16 + (size_t)m * HH + off) =
            make_uint4(pack_h2(v0.x, v0.y), pack_h2(v0.z, v0.w),
                       pack_h2(v1.x, v1.y), pack_h2(v1.z, v1.w));
    }
}

// ---------------- pointwise LSTM epilogue (R13 version) ---------------------

__device__ __forceinline__ float sigf(float v) {
    return 1.0f / (1.0f + __expf(-v));
}

__global__ void __launch_bounds__(256)
lstm_pointwise(const float* __restrict__ c0,
               const float* __restrict__ bi, const float* __restrict__ bf,
               const float* __restrict__ bc, const float* __restrict__ bo,
               const float* __restrict__ maskC, float* __restrict__ out)
{
    const int i4 = blockIdx.x * blockDim.x + threadIdx.x;   // over BH/4
    if (i4 >= BH / 4) return;
    const int k4 = i4 & (H_DIM / 4 - 1);

    const uint2 gi = ((const uint2*)(g_g16 + 0 * (size_t)BH))[i4];
    const uint2 gf = ((const uint2*)(g_g16 + 1 * (size_t)BH))[i4];
    const uint2 gc = ((const uint2*)(g_g16 + 2 * (size_t)BH))[i4];
    const uint2 go = ((const uint2*)(g_g16 + 3 * (size_t)BH))[i4];
    const float2 GI0 = __half22float2(*(const __half2*)&gi.x);
    const float2 GI1 = __half22float2(*(const __half2*)&gi.y);
    const float2 GF0 = __half22float2(*(const __half2*)&gf.x);
    const float2 GF1 = __half22float2(*(const __half2*)&gf.y);
    const float2 GC0 = __half22float2(*(const __half2*)&gc.x);
    const float2 GC1 = __half22float2(*(const __half2*)&gc.y);
    const float2 GO0 = __half22float2(*(const __half2*)&go.x);
    const float2 GO1 = __half22float2(*(const __half2*)&go.y);

    const float4 BI = ((const float4*)bi)[k4];
    const float4 BF = ((const float4*)bf)[k4];
    const float4 BC = ((const float4*)bc)[k4];
    const float4 BO = ((const float4*)bo)[k4];
    const float4 C0 = ((const float4*)c0)[i4];
    const float4 MC = ((const float4*)maskC)[i4];

    float4 h1, c1;
#define LSTM_DO(gi_, gf_, gc_, go_, cb) { \
        const float I = sigf((gi_) + BI.cb); \
        const float F = sigf((gf_) + BF.cb); \
        const float C = tanhf((gc_) + BC.cb) * MC.cb; \
        const float O = sigf((go_) + BO.cb); \
        const float cc = F * C0.cb + I * C; \
        c1.cb = cc; h1.cb = O * tanhf(cc); (void)0; }
    LSTM_DO(GI0.x, GF0.x, GC0.x, GO0.x, x)
    LSTM_DO(GI0.y, GF0.y, GC0.y, GO0.y, y)
    LSTM_DO(GI1.x, GF1.x, GC1.x, GO1.x, z)
    LSTM_DO(GI1.y, GF1.y, GC1.y, GO1.y, w)
#undef LSTM_DO

    ((float4*)out)[i4]          = h1;   // h1 at [0, BH)
    ((float4*)out)[BH / 4 + i4] = c1;   // c1 at [BH, 2*BH)
}

// ---------------- launch ----------------------------------------------------

extern "C" void kernel_launch(void* const* d_in, const int* in_sizes, int n_in,
                              void* d_out, int out_size)
{
    const float* x     = (const float*)d_in[0];
    const float* h0    = (const float*)d_in[1];
    const float* c0    = (const float*)d_in[2];
    const float* w_xi  = (const float*)d_in[3];
    const float* w_xf  = (const float*)d_in[4];
    const float* w_xc  = (const float*)d_in[5];
    const float* w_xo  = (const float*)d_in[6];
    const float* w_hi  = (const float*)d_in[7];
    const float* w_hf  = (const float*)d_in[8];
    const float* w_hc  = (const float*)d_in[9];
    const float* w_ho  = (const float*)d_in[10];
    const float* b_i   = (const float*)d_in[11];
    const float* b_f   = (const float*)d_in[12];
    const float* b_c   = (const float*)d_in[13];
    const float* b_o   = (const float*)d_in[14];
    const float* mHI   = (const float*)d_in[15];
    const float* mHF   = (const float*)d_in[16];
    const float* mHC   = (const float*)d_in[17];
    const float* mHO   = (const float*)d_in[18];
    const float* maskC = (const float*)d_in[19];

    prep_kernel<<<2048 + 4096, 256>>>(x, h0, mHI, mHF, mHC, mHO,
                                      w_xi, w_xf, w_xc, w_xo,
                                      w_hi, w_hf, w_hc, w_ho);

    cudaFuncSetAttribute(lstm_gemm,
                         cudaFuncAttributeMaxDynamicSharedMemorySize, SMEM_BYTES);
    dim3 grid(H_DIM / TN, B_DIM / TM, 4);   // (8, 16, 4) = 512 CTAs
    lstm_gemm<<<grid, 256, SMEM_BYTES>>>();

    const int n4 = BH / 4;
    lstm_pointwise<<<(n4 + 255) / 256, 256>>>(c0, b_i, b_f, b_c, b_o, maskC,
                                              (float*)d_out);
}

// round 17
// speedup vs baseline: 1.7488x; 1.0037x over previous
#include <cuda_runtime.h>
#include <cuda_fp16.h>
#include <cstdint>

// ============================================================================
// untied LSTM cell, GB300 — plain sm_103 target (no tcgen05 in this harness).
// fp16 mma.sync m16n8k16 + ldmatrix.x4, 3-stage cp.async mbarrier ring,
// XOR swizzle, 2 CTAs/SM (tile 128x128, warp tile 32x64, TK=64).
// R17 vs R16 (121.3us): persistent CTAs — grid 296, each CTA runs tiles
// {bid, bid+296} as ONE flat chunk stream through the same ring. Tile 2's
// prefetch overlaps tile 1's epilogue; wave-2 launch + pipeline refill gone.
// Inner loop body identical to R16 (the only schedule that fits 128 regs).
// ============================================================================

#define B_DIM 2048
#define H_DIM 1024
#define BH (B_DIM * H_DIM)
#define HH (H_DIM * H_DIM)

__device__ __align__(16) __half g_g16 [4u * BH];    // gate pre-acts fp16 (16MB)
__device__ __align__(16) __half g_x16 [BH];         // x fp16 (4 MB)
__device__ __align__(16) __half g_hm16[4u * BH];    // h0*mask[g] fp16 (16 MB)
__device__ __align__(16) __half g_w16 [8u * HH];    // Wx[4],Wh[4] fp16 (16 MB)

// ---------------- PTX helpers ----------------------------------------------

__device__ __forceinline__ uint32_t smem_u32(const void* p) {
    uint32_t a;
    asm("{ .reg .u64 t; cvta.to.shared.u64 t, %1; cvt.u32.u64 %0, t; }"
        : "=r"(a) : "l"(p));
    return a;
}

__device__ __forceinline__ void cp_async16(void* sdst, const void* gsrc) {
    asm volatile("cp.async.cg.shared.global [%0], [%1], 16;"
                 :: "r"(smem_u32(sdst)), "l"(gsrc));
}

__device__ __forceinline__ void ldm_x4(uint32_t* r, uint32_t addr) {
    asm volatile("ldmatrix.sync.aligned.m8n8.x4.shared.b16 {%0,%1,%2,%3}, [%4];"
                 : "=r"(r[0]), "=r"(r[1]), "=r"(r[2]), "=r"(r[3]) : "r"(addr));
}

__device__ __forceinline__ void mma_f16(float* c, const uint32_t* a,
                                        const uint32_t* b) {
    asm volatile(
        "mma.sync.aligned.m16n8k16.row.col.f32.f16.f16.f32 "
        "{%0,%1,%2,%3}, {%4,%5,%6,%7}, {%8,%9}, {%0,%1,%2,%3};"
        : "+f"(c[0]), "+f"(c[1]), "+f"(c[2]), "+f"(c[3])
        : "r"(a[0]), "r"(a[1]), "r"(a[2]), "r"(a[3]), "r"(b[0]), "r"(b[1]));
}

__device__ __forceinline__ uint32_t pack_h2(float lo, float hi) {
    const __half2 h = __float22half2_rn(make_float2(lo, hi));
    return *(const uint32_t*)&h;
}

// ---------------- mbarrier helpers ------------------------------------------

#define MBARRIER_INIT(mbar, count) \
    asm volatile("mbarrier.init.shared.b64 [%0], %1;" \
                 :: "r"((uint32_t)(mbar)), "r"((uint32_t)(count)) : "memory")

#define MBARRIER_ARRIVE(mbar) \
    asm volatile("{ .reg .b64 t; mbarrier.arrive.shared.b64 t, [%0]; }" \
                 :: "r"((uint32_t)(mbar)) : "memory")

#define CP_MBAR_ARRIVE_NOINC(mbar) \
    asm volatile("cp.async.mbarrier.arrive.noinc.shared.b64 [%0];" \
                 :: "r"((uint32_t)(mbar)) : "memory")

#define MBARRIER_WAIT_PARITY(mbar_addr, phase_parity) do { \
    uint32_t _mbar = (uint32_t)(mbar_addr); \
    uint32_t _parity = (uint32_t)(phase_parity); \
    uint32_t _done; \
    asm volatile( \
        "{\n\t.reg .pred p;\n\t" \
        "mbarrier.try_wait.parity.acquire.cta.shared::cta.b64 p, [%1], %2;\n\t" \
        "selp.b32 %0, 1, 0, p;\n\t}" \
        : "=r"(_done) : "r"(_mbar), "r"(_parity) : "memory"); \
    if (!_done) { \
        asm volatile( \
            "{\n\t.reg .pred P1;\n\t" \
            "WAIT_LOOP_%=:\n\t" \
            "mbarrier.try_wait.parity.acquire.cta.shared::cta.b64 P1, [%0], %1, 0x989680;\n\t" \
            "@P1 bra.uni WAIT_DONE_%=;\n\t" \
            "bra.uni WAIT_LOOP_%=;\n\t" \
            "WAIT_DONE_%=:\n\t}" \
            :: "r"(_mbar), "r"(_parity) : "memory"); \
    } \
} while (0)

// ---------------- GEMM config ----------------------------------------------
// Rows are exactly 128B; column-block cb (0..7, 16B each) is XOR-swizzled
// with (row & 7): conflict-free for both cp.async stores and ldmatrix reads.

static constexpr int TM = 128, TN = 128, TK = 64;
static constexpr int STAGES = 3;
static constexpr int A_BYTES = TM * 128;            // 16384
static constexpr int B_BYTES = TN * 128;            // 16384
static constexpr int STAGE_BYTES = A_BYTES + B_BYTES;       // 32768
static constexpr int MBAR_OFF   = STAGES * STAGE_BYTES;     // 98304
static constexpr int SMEM_BYTES = MBAR_OFF + 64;            // 98368 (x2 CTA ok)

static constexpr int GRID_P   = 296;                // 148 SMs x 2 CTAs
static constexpr int N_TILES  = 512;                // (2048/128)*(1024/128)*4

// tile id t (0..511): gate = t >> 7, m_tile = (t >> 3) & 15, n_tile = t & 7
__device__ __forceinline__ void tile_decode(int t, int& gate,
                                            int& arow0, int& brow0) {
    gate  = t >> 7;
    arow0 = ((t >> 3) & 15) * TM;
    brow0 = (t & 7) * TN;
}

// ---------------- GEMM kernel: persistent, 256 thr, 2 CTA/SM ---------------

__global__ void __launch_bounds__(256, 2)
lstm_gemm()
{
    extern __shared__ char smc[];
    const int tid  = threadIdx.x;
    const int lane = tid & 31;
    const int wid  = tid >> 5;          // 0..7
    const int wm   = wid >> 1;          // 0..3  (M warps, 32 rows)
    const int wn   = wid & 1;           // 0..1  (N warps, 64 cols)

    const int tile0 = blockIdx.x;                    // always valid
    const int tile1 = blockIdx.x + GRID_P;           // valid if < N_TILES
    const int NC    = (tile1 < N_TILES) ? 64 : 32;   // chunks this CTA runs

    const uint32_t sm_base  = smem_u32(smc);
    const uint32_t mb_full  = sm_base + MBAR_OFF;        // full[s]  = +s*8
    const uint32_t mb_empty = sm_base + MBAR_OFF + 24;   // empty[s] = +s*8

    if (tid == 0) {
        #pragma unroll
        for (int s = 0; s < STAGES; ++s) {
            MBARRIER_INIT(mb_full  + s * 8, 256);
            MBARRIER_INIT(mb_empty + s * 8, 256);
        }
    }
    __syncthreads();                    // init visible before any arrive

    // chunk c (0..NC-1): tile = (c<32)?tile0:tile1; local cl = c & 31;
    // cl 0..15: x @ Wx half, cl 16..31: hm @ Wh half. K-cols = (cl&15)*TK.
    auto issue = [&](int chunk, int stage) {
        const int t  = (chunk < 32) ? tile0 : tile1;
        const int cl = chunk & 31;
        int gate, arow0, brow0;
        tile_decode(t, gate, arow0, brow0);
        const int kc = (cl & 15) * TK;                    // halves
        const __half* Asrc = (cl < 16) ? g_x16 : g_hm16 + (size_t)gate * BH;
        const __half* Bsrc = g_w16 + (size_t)(cl < 16 ? gate : 4 + gate) * HH;
        char* As = smc + stage * STAGE_BYTES;
        char* Bs = As + A_BYTES;
        #pragma unroll
        for (int r = 0; r < 4; ++r) {                     // A: 1024 x 16B
            const int pos = tid + r * 256;
            const int row = pos >> 3, cb = pos & 7;
            cp_async16(As + row * 128 + ((cb ^ (row & 7)) << 4),
                       (const char*)(Asrc + (size_t)(arow0 + row) * 1024 + kc)
                           + cb * 16);
        }
        #pragma unroll
        for (int r = 0; r < 4; ++r) {                     // B: 1024 x 16B
            const int pos = tid + r * 256;
            const int row = pos >> 3, cb = pos & 7;
            cp_async16(Bs + row * 128 + ((cb ^ (row & 7)) << 4),
                       (const char*)(Bsrc + (size_t)(brow0 + row) * 1024 + kc)
                           + cb * 16);
        }
    };

    float acc[2][8][4];
    #pragma unroll
    for (int i = 0; i < 2; ++i)
        #pragma unroll
        for (int j = 0; j < 8; ++j)
            #pragma unroll
            for (int k = 0; k < 4; ++k) acc[i][j][k] = 0.f;

    // prologue: chunks 0,1 -> stages 0,1 (first uses: no empty wait)
    issue(0, 0); CP_MBAR_ARRIVE_NOINC(mb_full + 0 * 8);
    issue(1, 1); CP_MBAR_ARRIVE_NOINC(mb_full + 1 * 8);

    // ldmatrix lane bases (XOR key = lane & 7 for every fragment of a lane)
    const int      swz_key = lane & 7;
    const uint32_t a_row   = (uint32_t)(wm * 32 + (lane & 15)) * 128;
    const int      a_cb0   = lane >> 4;                   // 0/1
    const uint32_t b_row   = (uint32_t)(wn * 64 + (lane & 7) +
                                        ((lane >> 4) << 3)) * 128;
    const int      b_cb0   = (lane >> 3) & 1;             // 0/1

    // single-buffered fragments (R13 register budget, no spills)
    uint32_t af[2][4], bq[4][4];

    #define LOAD_FRAGS(ks, a_base, b_base) do {                             \
        const uint32_t a_sw =                                               \
            (uint32_t)((((ks) * 2 + a_cb0) ^ swz_key) << 4);                \
        const uint32_t b_sw =                                               \
            (uint32_t)((((ks) * 2 + b_cb0) ^ swz_key) << 4);                \
        ldm_x4(af[0], (a_base) + 0u * 16 * 128 + a_sw);                     \
        ldm_x4(af[1], (a_base) + 1u * 16 * 128 + a_sw);                     \
        ldm_x4(bq[0], (b_base) + 0u * 16 * 128 + b_sw);                     \
        ldm_x4(bq[1], (b_base) + 1u * 16 * 128 + b_sw);                     \
        ldm_x4(bq[2], (b_base) + 2u * 16 * 128 + b_sw);                     \
        ldm_x4(bq[3], (b_base) + 3u * 16 * 128 + b_sw);                     \
    } while (0)

    int s = 0, u = 0;                   // consumer cursor (stage, phase use)
    int s2 = 2, u2 = 0;                 // producer cursor (chunk c+2)

    for (int c = 0; c < NC; ++c) {
        // consumer: wait until stage s holds chunk c
        MBARRIER_WAIT_PARITY(mb_full + s * 8, u & 1);

        const uint32_t stg = sm_base + (uint32_t)(s * STAGE_BYTES);
        const uint32_t a_base = stg + a_row;
        const uint32_t b_base = stg + A_BYTES + b_row;

        #pragma unroll
        for (int ks = 0; ks < 4; ++ks) {                  // K=16 per step
            LOAD_FRAGS(ks, a_base, b_base);
            #pragma unroll
            for (int mf = 0; mf < 2; ++mf)
                #pragma unroll
                for (int nf = 0; nf < 8; ++nf)
                    mma_f16(acc[mf][nf], af[mf],
                            &bq[nf >> 1][(nf & 1) * 2]);
        }

        // done reading stage s (mma issue implies LDSM data landed)
        MBARRIER_ARRIVE(mb_empty + s * 8);

        // producer: refill stage s2 with chunk c+2 (crosses tile boundary,
        // so tile1's first chunks load during tile0's epilogue below)
        if (c + 2 < NC) {
            if (u2 > 0)
                MBARRIER_WAIT_PARITY(mb_empty + s2 * 8, (u2 - 1) & 1);
            issue(c + 2, s2);
            CP_MBAR_ARRIVE_NOINC(mb_full + s2 * 8);
        }

        // tile finished? write its pre-activations, reset accumulators.
        if ((c & 31) == 31) {
            const int t = (c < 32) ? tile0 : tile1;
            int gate, arow0, brow0;
            tile_decode(t, gate, arow0, brow0);
            const int g = lane >> 2, t2 = (lane & 3) * 2;
            #pragma unroll
            for (int mf = 0; mf < 2; ++mf) {
                const int row = arow0 + wm * 32 + mf * 16 + g;
                __half* orow =
                    g_g16 + ((size_t)gate * B_DIM + row) * H_DIM + brow0;
                #pragma unroll
                for (int nf = 0; nf < 8; ++nf) {
                    const int col = wn * 64 + nf * 8 + t2;
                    *(uint32_t*)(orow + col) =
                        pack_h2(acc[mf][nf][0], acc[mf][nf][1]);
                    *(uint32_t*)(orow + col + 8 * H_DIM) =
                        pack_h2(acc[mf][nf][2], acc[mf][nf][3]);
                    acc[mf][nf][0] = 0.f; acc[mf][nf][1] = 0.f;
                    acc[mf][nf][2] = 0.f; acc[mf][nf][3] = 0.f;
                }
            }
        }

        if (++s == STAGES) { s = 0; ++u; }
        if (++s2 == STAGES) { s2 = 0; ++u2; }
    }
    #undef LOAD_FRAGS
}

// ------- fused pre-pass: x->fp16, hm[g]=h0*mask[g]->fp16, weights->fp16 -----

__global__ void __launch_bounds__(256)
prep_kernel(const float* __restrict__ x,  const float* __restrict__ h0,
            const float* __restrict__ mi, const float* __restrict__ mf,
            const float* __restrict__ mc, const float* __restrict__ mo,
            const float* __restrict__ wxi, const float* __restrict__ wxf,
            const float* __restrict__ wxc, const float* __restrict__ wxo,
            const float* __restrict__ whi, const float* __restrict__ whf,
            const float* __restrict__ whc, const float* __restrict__ who)
{
    const int bid = blockIdx.x;
    if (bid < 2048) {                               // x + hm part (BH/4 elems)
        const int i = bid * 256 + threadIdx.x;
        const float4 xv = ((const float4*)x)[i];
        ((uint2*)g_x16)[i] =
            make_uint2(pack_h2(xv.x, xv.y), pack_h2(xv.z, xv.w));
        const float4 h = ((const float4*)h0)[i];
        const float4 M[4] = { ((const float4*)mi)[i], ((const float4*)mf)[i],
                              ((const float4*)mc)[i], ((const float4*)mo)[i] };
        #pragma unroll
        for (int gate = 0; gate < 4; ++gate) {
            ((uint2*)(g_hm16 + (size_t)gate * BH))[i] =
                make_uint2(pack_h2(h.x * M[gate].x, h.y * M[gate].y),
                           pack_h2(h.z * M[gate].z, h.w * M[gate].w));
        }
    } else {                                        // weight conversion part
        const int wb = bid - 2048;                  // 0..4095
        const int m = wb >> 9;                      // matrix 0..7
        const float* src =
            m == 0 ? wxi : m == 1 ? wxf : m == 2 ? wxc : m == 3 ? wxo :
            m == 4 ? whi : m == 5 ? whf : m == 6 ? whc : who;
        const int off = ((wb & 511) * 256 + threadIdx.x) * 8;
        const float4 v0 = *(const float4*)(src + off);
        const float4 v1 = *(const float4*)(src + off + 4);
        *(uint4*)(g_w16 + (size_t)m * HH + off) =
            make_uint4(pack_h2(v0.x, v0.y), pack_h2(v0.z, v0.w),
                       pack_h2(v1.x, v1.y), pack_h2(v1.z, v1.w));
    }
}

// ---------------- pointwise LSTM epilogue -----------------------------------

__device__ __forceinline__ float sigf(float v) {
    return 1.0f / (1.0f + __expf(-v));
}

__global__ void __launch_bounds__(256)
lstm_pointwise(const float* __restrict__ c0,
               const float* __restrict__ bi, const float* __restrict__ bf,
               const float* __restrict__ bc, const float* __restrict__ bo,
               const float* __restrict__ maskC, float* __restrict__ out)
{
    const int i4 = blockIdx.x * blockDim.x + threadIdx.x;   // over BH/4
    if (i4 >= BH / 4) return;
    const int k4 = i4 & (H_DIM / 4 - 1);

    const uint2 gi = ((const uint2*)(g_g16 + 0 * (size_t)BH))[i4];
    const uint2 gf = ((const uint2*)(g_g16 + 1 * (size_t)BH))[i4];
    const uint2 gc = ((const uint2*)(g_g16 + 2 * (size_t)BH))[i4];
    const uint2 go = ((const uint2*)(g_g16 + 3 * (size_t)BH))[i4];
    const float2 GI0 = __half22float2(*(const __half2*)&gi.x);
    const float2 GI1 = __half22float2(*(const __half2*)&gi.y);
    const float2 GF0 = __half22float2(*(const __half2*)&gf.x);
    const float2 GF1 = __half22float2(*(const __half2*)&gf.y);
    const float2 GC0 = __half22float2(*(const __half2*)&gc.x);
    const float2 GC1 = __half22float2(*(const __half2*)&gc.y);
    const float2 GO0 = __half22float2(*(const __half2*)&go.x);
    const float2 GO1 = __half22float2(*(const __half2*)&go.y);

    const float4 BI = ((const float4*)bi)[k4];
    const float4 BF = ((const float4*)bf)[k4];
    const float4 BC = ((const float4*)bc)[k4];
    const float4 BO = ((const float4*)bo)[k4];
    const float4 C0 = ((const float4*)c0)[i4];
    const float4 MC = ((const float4*)maskC)[i4];

    float4 h1, c1;
#define LSTM_DO(gi_, gf_, gc_, go_, cb) { \
        const float I = sigf((gi_) + BI.cb); \
        const float F = sigf((gf_) + BF.cb); \
        const float C = tanhf((gc_) + BC.cb) * MC.cb; \
        const float O = sigf((go_) + BO.cb); \
        const float cc = F * C0.cb + I * C; \
        c1.cb = cc; h1.cb = O * tanhf(cc); (void)0; }
    LSTM_DO(GI0.x, GF0.x, GC0.x, GO0.x, x)
    LSTM_DO(GI0.y, GF0.y, GC0.y, GO0.y, y)
    LSTM_DO(GI1.x, GF1.x, GC1.x, GO1.x, z)
    LSTM_DO(GI1.y, GF1.y, GC1.y, GO1.y, w)
#undef LSTM_DO

    ((float4*)out)[i4]          = h1;   // h1 at [0, BH)
    ((float4*)out)[BH / 4 + i4] = c1;   // c1 at [BH, 2*BH)
}

// ---------------- launch ----------------------------------------------------

extern "C" void kernel_launch(void* const* d_in, const int* in_sizes, int n_in,
                              void* d_out, int out_size)
{
    const float* x     = (const float*)d_in[0];
    const float* h0    = (const float*)d_in[1];
    const float* c0    = (const float*)d_in[2];
    const float* w_xi  = (const float*)d_in[3];
    const float* w_xf  = (const float*)d_in[4];
    const float* w_xc  = (const float*)d_in[5];
    const float* w_xo  = (const float*)d_in[6];
    const float* w_hi  = (const float*)d_in[7];
    const float* w_hf  = (const float*)d_in[8];
    const float* w_hc  = (const float*)d_in[9];
    const float* w_ho  = (const float*)d_in[10];
    const float* b_i   = (const float*)d_in[11];
    const float* b_f   = (const float*)d_in[12];
    const float* b_c   = (const float*)d_in[13];
    const float* b_o   = (const float*)d_in[14];
    const float* mHI   = (const float*)d_in[15];
    const float* mHF   = (const float*)d_in[16];
    const float* mHC   = (const float*)d_in[17];
    const float* mHO   = (const float*)d_in[18];
    const float* maskC = (const float*)d_in[19];

    prep_kernel<<<2048 + 4096, 256>>>(x, h0, mHI, mHF, mHC, mHO,
                                      w_xi, w_xf, w_xc, w_xo,
                                      w_hi, w_hf, w_hc, w_ho);

    cudaFuncSetAttribute(lstm_gemm,
                         cudaFuncAttributeMaxDynamicSharedMemorySize, SMEM_BYTES);
    lstm_gemm<<<GRID_P, 256, SMEM_BYTES>>>();

    const int n4 = BH / 4;
    lstm_pointwise<<<(n4 + 255) / 256, 256>>>(c0, b_i, b_f, b_c, b_o, maskC,
                                              (float*)d_out);
}